// round 14
// baseline (speedup 1.0000x reference)
#include <cuda_runtime.h>
#include <math.h>

#define FULLMASK 0xffffffffu
#define LSZ 64
#define HSZ 32
#define BATCH 1024

// ---- packed f32x2 helpers (sm_103a) ----
__device__ __forceinline__ float2 ffma2(float2 a, float2 b, float2 c) {
    unsigned long long ua = reinterpret_cast<unsigned long long&>(a);
    unsigned long long ub = reinterpret_cast<unsigned long long&>(b);
    unsigned long long uc = reinterpret_cast<unsigned long long&>(c);
    asm("fma.rn.f32x2 %0, %1, %2, %0;" : "+l"(uc) : "l"(ua), "l"(ub));
    return reinterpret_cast<float2&>(uc);
}
__device__ __forceinline__ float2 fadd2(float2 a, float2 b) {
    unsigned long long ua = reinterpret_cast<unsigned long long&>(a);
    unsigned long long ub = reinterpret_cast<unsigned long long&>(b);
    unsigned long long ud;
    asm("add.rn.f32x2 %0, %1, %2;" : "=l"(ud) : "l"(ua), "l"(ub));
    return reinterpret_cast<float2&>(ud);
}

// 32-wide dot of broadcast h-vector (8 x LDS.128) against per-lane column W.
__device__ __forceinline__ float matvec32(const float2* W, const float* hrow) {
    const float4* hp = reinterpret_cast<const float4*>(hrow);
    float4 g0 = hp[0], g1 = hp[1], g2 = hp[2], g3 = hp[3];
    float4 g4 = hp[4], g5 = hp[5], g6 = hp[6], g7 = hp[7];
    float2 a0 = make_float2(0.f, 0.f), a1 = a0, a2 = a0, a3 = a0;
    a0 = ffma2(W[0],  make_float2(g0.x, g0.y), a0);
    a1 = ffma2(W[1],  make_float2(g0.z, g0.w), a1);
    a2 = ffma2(W[2],  make_float2(g1.x, g1.y), a2);
    a3 = ffma2(W[3],  make_float2(g1.z, g1.w), a3);
    a0 = ffma2(W[4],  make_float2(g2.x, g2.y), a0);
    a1 = ffma2(W[5],  make_float2(g2.z, g2.w), a1);
    a2 = ffma2(W[6],  make_float2(g3.x, g3.y), a2);
    a3 = ffma2(W[7],  make_float2(g3.z, g3.w), a3);
    a0 = ffma2(W[8],  make_float2(g4.x, g4.y), a0);
    a1 = ffma2(W[9],  make_float2(g4.z, g4.w), a1);
    a2 = ffma2(W[10], make_float2(g5.x, g5.y), a2);
    a3 = ffma2(W[11], make_float2(g5.z, g5.w), a3);
    a0 = ffma2(W[12], make_float2(g6.x, g6.y), a0);
    a1 = ffma2(W[13], make_float2(g6.z, g6.w), a1);
    a2 = ffma2(W[14], make_float2(g7.x, g7.y), a2);
    a3 = ffma2(W[15], make_float2(g7.z, g7.w), a3);
    float2 s = fadd2(fadd2(a0, a1), fadd2(a2, a3));
    return s.x + s.y;
}

__global__ __launch_bounds__(64)
void rnn2d_kernel(const int*   __restrict__ x,     // [B,64,64]
                  const float* __restrict__ Win,   // [4,32]
                  const float* __restrict__ WcH,   // [32,32]
                  const float* __restrict__ WcV,   // [32,32]
                  const float* __restrict__ bV,    // [32]
                  const float* __restrict__ Wout,  // [32,2]
                  const float* __restrict__ bout,  // [2]
                  float*       __restrict__ out)   // [B]
{
    // s_P[buf][scan j][lane]: vertical contribution (WcV^T·h of row above),
    // snake-mirrored at write time (warp 1). s_h: current row h history.
    __shared__ float s_P[2][LSZ][HSZ];   // 16 KB
    __shared__ float s_h[LSZ][HSZ];      //  8 KB
    __shared__ float s_wod[HSZ];

    const int tid  = threadIdx.x;
    const int lane = tid & 31;
    const int wid  = tid >> 5;           // 0: recurrence+epilogue, 1: V matvec
    const int b    = blockIdx.x;

    // Each warp loads only its matrix into the SAME register array.
    float2 W[16];
    const float* Wsrc = wid ? WcV : WcH;
#pragma unroll
    for (int m = 0; m < 16; ++m)
        W[m] = make_float2(Wsrc[(2 * m) * HSZ + lane],
                           Wsrc[(2 * m + 1) * HSZ + lane]);

    float W0 = 0.f, W1 = 0.f, W2 = 0.f, W3 = 0.f, bVl = 0.f, bd = 0.f;
    if (wid == 0) {
        W0 = Win[lane];            W1 = Win[HSZ + lane];
        W2 = Win[2 * HSZ + lane];  W3 = Win[3 * HSZ + lane];
        bVl = bV[lane];
        s_wod[lane] = Wout[lane * 2 + 0] - Wout[lane * 2 + 1];
        bd = bout[0] - bout[1];
    }

    // zero initial P buffer (row 0 reads zeros); both warps split the work
    for (int c = wid; c < LSZ; c += 2) s_P[0][c][lane] = 0.f;

    const int* xb = x + (size_t)b * (LSZ * LSZ);
    int cur0 = 0, cur1 = 0;
    if (wid == 0) { cur0 = xb[lane]; cur1 = xb[HSZ + lane]; }
    unsigned long long rawprev = 0ull;
    float lanesum = 0.f;
    __syncthreads();

#pragma unroll 1
    for (int r = 0; r < LSZ; ++r) {
        const int pb = r & 1, nb = pb ^ 1;
        unsigned long long cm = 0ull, pm = 0ull;
        float eW2 = 0.f, eW3 = 0.f;

        if (wid == 0) {
            unsigned int b0 = __ballot_sync(FULLMASK, cur0);
            unsigned int b1 = __ballot_sync(FULLMASK, cur1);
            unsigned long long raw = (unsigned long long)b0 |
                                     ((unsigned long long)b1 << 32);
            if (r < LSZ - 1) {
                cur0 = xb[(r + 1) * LSZ + lane];
                cur1 = xb[(r + 1) * LSZ + HSZ + lane];
            }
            const bool fwd = ((r & 1) == 0);
            cm = fwd ? raw : __brevll(raw);          // current row, scan order
            pm = fwd ? rawprev : __brevll(rawprev);  // row above, scan order
            rawprev = raw;
            eW2 = r ? W2 : 0.f;
            eW3 = r ? W3 : 0.f;
            // ---- step 0: h0 = elu(P[0] + bV + vsel) ----
            float v = s_P[pb][0][lane] + bVl + ((pm & 1ull) ? eW3 : eW2);
            float e = __expf(v) - 1.0f;
            s_h[0][lane] = (v > 0.f) ? v : e;
        }
        unsigned long long hm = cm;        // bit0 = hsel at step 1
        unsigned long long vm = pm >> 1;   // bit0 = vsel at step 1
        __syncthreads();                   // h0 visible to both warps

        // ---- steps 1..63: warp0 recurrence, warp1 V-matvec of h_{j-1} ----
#pragma unroll 2
        for (int j = 1; j < LSZ; ++j) {
            float sv = matvec32(W, &s_h[j - 1][0]);
            if (wid == 0) {
                float base = s_P[pb][j][lane] + bVl
                           + ((hm & 1ull) ? W1 : W0)
                           + ((vm & 1ull) ? eW3 : eW2);
                hm >>= 1; vm >>= 1;
                float v = sv + base;
                float e = __expf(v) - 1.0f;
                s_h[j][lane] = (v > 0.f) ? v : e;
            } else {
                // h_{j-1} (scan j-1) -> next row scan index 64-j (snake mirror)
                s_P[nb][LSZ - j][lane] = sv;
            }
            __syncthreads();               // h_j + P stores ordered for next iter
        }

        // ---- row tail: warp1 finishes P[0] (h_63); warp0 does epilogue ----
        if (wid == 1) {
            s_P[nb][0][lane] = matvec32(W, &s_h[LSZ - 1][0]);
        } else {
            const float* hb = &s_h[0][0];
            const int l32 = lane * HSZ;
            float d0 = 0.f, d1 = 0.f;      // scan columns lane, lane+32
#pragma unroll
            for (int m = 0; m < 32; ++m) {
                int   idx = lane ^ m;      // conflict-free rotation
                float wv  = s_wod[idx];
                d0 = fmaf(hb[l32 + idx],             wv, d0);
                d1 = fmaf(hb[l32 + HSZ * HSZ + idx], wv, d1);
            }
            float u0 = d0 + bd, u1 = d1 + bd;   // z0 - z1 per column
            int sp0 = (int)((cm >> lane) & 1ull);
            int sp1 = (int)((cm >> (lane + 32)) & 1ull);
            float t0 = sp0 ? u0 : -u0;
            float t1 = sp1 ? u1 : -u1;
            float lp0 = -fmaxf(t0, 0.f) - log1pf(__expf(-fabsf(t0)));
            float lp1 = -fmaxf(t1, 0.f) - log1pf(__expf(-fabsf(t1)));
            if (isnan(lp0)) lp0 = -35.f;
            if (isnan(lp1)) lp1 = -35.f;
            lanesum += lp0 + lp1;
        }
        __syncthreads();                   // P complete + s_h free before next row
    }

    if (wid == 0) {
        float tot = lanesum;
#pragma unroll
        for (int off = 16; off; off >>= 1)
            tot += __shfl_xor_sync(FULLMASK, tot, off);
        if (lane == 0) out[b] = 0.5f * tot;
    }
}

extern "C" void kernel_launch(void* const* d_in, const int* in_sizes, int n_in,
                              void* d_out, int out_size)
{
    const int*   x    = (const int*)  d_in[0];
    const float* Win  = (const float*)d_in[1];
    const float* WcH  = (const float*)d_in[2];
    const float* WcV  = (const float*)d_in[3];
    const float* bV   = (const float*)d_in[4];
    const float* Wout = (const float*)d_in[5];
    const float* bout = (const float*)d_in[6];

    rnn2d_kernel<<<BATCH, 64>>>(x, Win, WcH, WcV, bV, Wout, bout, (float*)d_out);
}

// round 15
// speedup vs baseline: 1.0072x; 1.0072x over previous
#include <cuda_runtime.h>
#include <math.h>

#define FULLMASK 0xffffffffu
#define LSZ 64
#define HSZ 32
#define BATCH 1024
#define CHUNK 16

// ---- packed f32x2 helpers (sm_103a) ----
__device__ __forceinline__ float2 ffma2(float2 a, float2 b, float2 c) {
    unsigned long long ua = reinterpret_cast<unsigned long long&>(a);
    unsigned long long ub = reinterpret_cast<unsigned long long&>(b);
    unsigned long long uc = reinterpret_cast<unsigned long long&>(c);
    asm("fma.rn.f32x2 %0, %1, %2, %0;" : "+l"(uc) : "l"(ua), "l"(ub));
    return reinterpret_cast<float2&>(uc);
}
__device__ __forceinline__ float2 fadd2(float2 a, float2 b) {
    unsigned long long ua = reinterpret_cast<unsigned long long&>(a);
    unsigned long long ub = reinterpret_cast<unsigned long long&>(b);
    unsigned long long ud;
    asm("add.rn.f32x2 %0, %1, %2;" : "=l"(ud) : "l"(ua), "l"(ub));
    return reinterpret_cast<float2&>(ud);
}

// 32-wide dot of broadcast h-vector (8 x LDS.128) against per-lane column W.
__device__ __forceinline__ float matvec32(const float2* W, const float* hrow) {
    const float4* hp = reinterpret_cast<const float4*>(hrow);
    float4 g0 = hp[0], g1 = hp[1], g2 = hp[2], g3 = hp[3];
    float4 g4 = hp[4], g5 = hp[5], g6 = hp[6], g7 = hp[7];
    float2 a0 = make_float2(0.f, 0.f), a1 = a0, a2 = a0, a3 = a0;
    a0 = ffma2(W[0],  make_float2(g0.x, g0.y), a0);
    a1 = ffma2(W[1],  make_float2(g0.z, g0.w), a1);
    a2 = ffma2(W[2],  make_float2(g1.x, g1.y), a2);
    a3 = ffma2(W[3],  make_float2(g1.z, g1.w), a3);
    a0 = ffma2(W[4],  make_float2(g2.x, g2.y), a0);
    a1 = ffma2(W[5],  make_float2(g2.z, g2.w), a1);
    a2 = ffma2(W[6],  make_float2(g3.x, g3.y), a2);
    a3 = ffma2(W[7],  make_float2(g3.z, g3.w), a3);
    a0 = ffma2(W[8],  make_float2(g4.x, g4.y), a0);
    a1 = ffma2(W[9],  make_float2(g4.z, g4.w), a1);
    a2 = ffma2(W[10], make_float2(g5.x, g5.y), a2);
    a3 = ffma2(W[11], make_float2(g5.z, g5.w), a3);
    a0 = ffma2(W[12], make_float2(g6.x, g6.y), a0);
    a1 = ffma2(W[13], make_float2(g6.z, g6.w), a1);
    a2 = ffma2(W[14], make_float2(g7.x, g7.y), a2);
    a3 = ffma2(W[15], make_float2(g7.z, g7.w), a3);
    float2 s = fadd2(fadd2(a0, a1), fadd2(a2, a3));
    return s.x + s.y;
}

__global__ __launch_bounds__(64)
void rnn2d_kernel(const int*   __restrict__ x,     // [B,64,64]
                  const float* __restrict__ Win,   // [4,32]
                  const float* __restrict__ WcH,   // [32,32]
                  const float* __restrict__ WcV,   // [32,32]
                  const float* __restrict__ bV,    // [32]
                  const float* __restrict__ Wout,  // [32,2]
                  const float* __restrict__ bout,  // [2]
                  float*       __restrict__ out)   // [B]
{
    // s_P[buf][scan j][lane]: vertical term WcV^T·h of the row above,
    // snake-mirrored (P[63-k] <- h_k), produced by warp 1 chunk-wise.
    __shared__ float s_P[2][LSZ][HSZ];   // 16 KB
    __shared__ float s_h[LSZ][HSZ];      //  8 KB
    __shared__ float s_wod[HSZ];

    const int tid  = threadIdx.x;
    const int lane = tid & 31;
    const int wid  = tid >> 5;           // 0: recurrence+epilogue, 1: V matvec
    const int b    = blockIdx.x;

    // Each warp loads only its matrix into the SAME register array.
    float2 W[16];
    const float* Wsrc = wid ? WcV : WcH;
#pragma unroll
    for (int m = 0; m < 16; ++m)
        W[m] = make_float2(Wsrc[(2 * m) * HSZ + lane],
                           Wsrc[(2 * m + 1) * HSZ + lane]);

    float W0 = 0.f, W1 = 0.f, W2 = 0.f, W3 = 0.f, bVl = 0.f, bd = 0.f;
    if (wid == 0) {
        W0 = Win[lane];            W1 = Win[HSZ + lane];
        W2 = Win[2 * HSZ + lane];  W3 = Win[3 * HSZ + lane];
        bVl = bV[lane];
        s_wod[lane] = Wout[lane * 2 + 0] - Wout[lane * 2 + 1];
        bd = bout[0] - bout[1];
    }

    for (int c = wid; c < LSZ; c += 2) s_P[0][c][lane] = 0.f;  // row 0 zeros

    const int* xb = x + (size_t)b * (LSZ * LSZ);
    int cur0 = 0, cur1 = 0;
    if (wid == 0) { cur0 = xb[lane]; cur1 = xb[HSZ + lane]; }
    unsigned long long rawprev = 0ull;
    float lanesum = 0.f;
    __syncthreads();

#pragma unroll 1
    for (int r = 0; r < LSZ; ++r) {
        const int pb = r & 1, nb = pb ^ 1;
        unsigned long long cm = 0ull, pm = 0ull, hm = 0ull, vm = 0ull;
        float eW2 = 0.f, eW3 = 0.f;

        if (wid == 0) {
            unsigned int b0 = __ballot_sync(FULLMASK, cur0);
            unsigned int b1 = __ballot_sync(FULLMASK, cur1);
            unsigned long long raw = (unsigned long long)b0 |
                                     ((unsigned long long)b1 << 32);
            if (r < LSZ - 1) {
                cur0 = xb[(r + 1) * LSZ + lane];
                cur1 = xb[(r + 1) * LSZ + HSZ + lane];
            }
            const bool fwd = ((r & 1) == 0);
            cm = fwd ? raw : __brevll(raw);          // current row, scan order
            pm = fwd ? rawprev : __brevll(rawprev);  // row above, scan order
            rawprev = raw;
            eW2 = r ? W2 : 0.f;
            eW3 = r ? W3 : 0.f;
            hm = cm;        // bit0 = hsel at step 1
            vm = pm >> 1;   // bit0 = vsel at step 1
        }

        // ---- 4 chunks: warp0 computes h[16c..16c+15]; after the barrier,
        //      warp1 processes that chunk concurrently with warp0's next. ----
#pragma unroll 1
        for (int c = 0; c < LSZ / CHUNK; ++c) {
            if (wid == 0) {
                const int j0 = c * CHUNK;
                int j = j0;
                if (c == 0) {
                    float v = s_P[pb][0][lane] + bVl + ((pm & 1ull) ? eW3 : eW2);
                    float e = __expf(v) - 1.0f;
                    s_h[0][lane] = (v > 0.f) ? v : e;
                    j = 1;
                }
#pragma unroll 3
                for (; j < j0 + CHUNK; ++j) {
                    float Pj   = s_P[pb][j][lane];
                    float hsel = (hm & 1ull) ? W1 : W0;
                    float vsel = (vm & 1ull) ? eW3 : eW2;
                    hm >>= 1; vm >>= 1;
                    float base = (Pj + bVl) + (hsel + vsel);
                    __syncwarp();              // own-warp h_{j-1} visible
                    float sh = matvec32(W, &s_h[j - 1][0]);
                    float v  = sh + base;
                    float e  = __expf(v) - 1.0f;
                    s_h[j][lane] = (v > 0.f) ? v : e;
                }
            }
            __syncthreads();                   // publish chunk c to warp 1
            if (wid == 1) {
                const int k0 = c * CHUNK;
#pragma unroll 4
                for (int k = k0; k < k0 + CHUNK; ++k)
                    s_P[nb][(LSZ - 1) - k][lane] = matvec32(W, &s_h[k][0]);
            }
        }

        // ---- warp0 epilogue (concurrent with warp1 chunk 3) ----
        if (wid == 0) {
            __syncwarp();
            const float* hb = &s_h[0][0];
            const int l32 = lane * HSZ;
            float d0 = 0.f, d1 = 0.f;          // scan columns lane, lane+32
#pragma unroll
            for (int m = 0; m < 32; ++m) {
                int   idx = lane ^ m;          // conflict-free rotation
                float wv  = s_wod[idx];
                d0 = fmaf(hb[l32 + idx],             wv, d0);
                d1 = fmaf(hb[l32 + HSZ * HSZ + idx], wv, d1);
            }
            float u0 = d0 + bd, u1 = d1 + bd;  // z0 - z1 per column
            int sp0 = (int)((cm >> lane) & 1ull);
            int sp1 = (int)((cm >> (lane + 32)) & 1ull);
            float t0 = sp0 ? u0 : -u0;
            float t1 = sp1 ? u1 : -u1;
            float lp0 = -fmaxf(t0, 0.f) - log1pf(__expf(-fabsf(t0)));
            float lp1 = -fmaxf(t1, 0.f) - log1pf(__expf(-fabsf(t1)));
            if (isnan(lp0)) lp0 = -35.f;
            if (isnan(lp1)) lp1 = -35.f;
            lanesum += lp0 + lp1;
        }
        __syncthreads();                       // P complete; s_h free for next row
    }

    if (wid == 0) {
        float tot = lanesum;
#pragma unroll
        for (int off = 16; off; off >>= 1)
            tot += __shfl_xor_sync(FULLMASK, tot, off);
        if (lane == 0) out[b] = 0.5f * tot;
    }
}

extern "C" void kernel_launch(void* const* d_in, const int* in_sizes, int n_in,
                              void* d_out, int out_size)
{
    const int*   x    = (const int*)  d_in[0];
    const float* Win  = (const float*)d_in[1];
    const float* WcH  = (const float*)d_in[2];
    const float* WcV  = (const float*)d_in[3];
    const float* bV   = (const float*)d_in[4];
    const float* Wout = (const float*)d_in[5];
    const float* bout = (const float*)d_in[6];

    rnn2d_kernel<<<BATCH, 64>>>(x, Win, WcH, WcV, bV, Wout, bout, (float*)d_out);
}

// round 16
// speedup vs baseline: 1.4501x; 1.4397x over previous
#include <cuda_runtime.h>
#include <math.h>

#define FULLMASK 0xffffffffu
#define LSZ 64
#define HSZ 32
#define BATCH 1024

// ---- packed f32x2 helpers (sm_103a) ----
__device__ __forceinline__ float2 ffma2(float2 a, float2 b, float2 c) {
    unsigned long long ua = reinterpret_cast<unsigned long long&>(a);
    unsigned long long ub = reinterpret_cast<unsigned long long&>(b);
    unsigned long long uc = reinterpret_cast<unsigned long long&>(c);
    asm("fma.rn.f32x2 %0, %1, %2, %0;" : "+l"(uc) : "l"(ua), "l"(ub));
    return reinterpret_cast<float2&>(uc);
}
__device__ __forceinline__ float2 fadd2(float2 a, float2 b) {
    unsigned long long ua = reinterpret_cast<unsigned long long&>(a);
    unsigned long long ub = reinterpret_cast<unsigned long long&>(b);
    unsigned long long ud;
    asm("add.rn.f32x2 %0, %1, %2;" : "=l"(ud) : "l"(ua), "l"(ub));
    return reinterpret_cast<float2&>(ud);
}

__global__ __launch_bounds__(32)
void rnn2d_kernel(const int*   __restrict__ x,     // [B,64,64]
                  const float* __restrict__ Win,   // [4,32]
                  const float* __restrict__ WcH,   // [32,32]
                  const float* __restrict__ WcV,   // [32,32]
                  const float* __restrict__ bV,    // [32]
                  const float* __restrict__ Wout,  // [32,2]
                  const float* __restrict__ bout,  // [2]
                  float*       __restrict__ out)   // [B]
{
    // s_P[buf][scan j][lane]: vertical contribution (WcV^T·h of row above),
    // snake-mirrored at write time. Same-lane read/write only.
    __shared__ float s_P[2][LSZ][HSZ];   // 16 KB
    __shared__ float s_h[LSZ][HSZ];      //  8 KB  h history of current row
    __shared__ float s_wod[HSZ];

    const int lane = threadIdx.x;        // owns hidden index `lane`
    const int b    = blockIdx.x;

    // ---- weights -> registers, k-pairs packed for FFMA2 ----
    float2 WH[16], WV[16];
#pragma unroll
    for (int m = 0; m < 16; ++m) {
        WH[m] = make_float2(WcH[(2 * m) * HSZ + lane], WcH[(2 * m + 1) * HSZ + lane]);
        WV[m] = make_float2(WcV[(2 * m) * HSZ + lane], WcV[(2 * m + 1) * HSZ + lane]);
    }
    const float W0 = Win[lane], W1 = Win[HSZ + lane];
    const float W2 = Win[2 * HSZ + lane], W3 = Win[3 * HSZ + lane];
    const float bVl = bV[lane];
    s_wod[lane] = Wout[lane * 2 + 0] - Wout[lane * 2 + 1];
    const float bd = bout[0] - bout[1];

#pragma unroll
    for (int c = 0; c < LSZ; ++c) s_P[0][c][lane] = 0.f;   // row 0: zero carry

    const int* xb = x + (size_t)b * (LSZ * LSZ);
    int cur0 = xb[lane];
    int cur1 = xb[HSZ + lane];
    unsigned long long rawprev = 0ull;
    float lanesum = 0.f;
    __syncwarp();

#pragma unroll 1
    for (int r = 0; r < LSZ; ++r) {
        unsigned int b0 = __ballot_sync(FULLMASK, cur0);
        unsigned int b1 = __ballot_sync(FULLMASK, cur1);
        unsigned long long raw = (unsigned long long)b0 |
                                 ((unsigned long long)b1 << 32);
        if (r < LSZ - 1) {
            cur0 = xb[(r + 1) * LSZ + lane];
            cur1 = xb[(r + 1) * LSZ + HSZ + lane];
        }
        const bool fwd = ((r & 1) == 0);
        const unsigned long long cm = fwd ? raw : __brevll(raw);         // cur row, scan order
        const unsigned long long pm = fwd ? rawprev : __brevll(rawprev); // row above, scan order
        rawprev = raw;
        const float eW2 = r ? W2 : 0.f;    // row 0: vertical one-hot contributes 0
        const float eW3 = r ? W3 : 0.f;

        const int pb = r & 1, nb = pb ^ 1;

        // ---- step 0: h0 = elu(P[0] + bV + vsel), no horizontal term ----
        {
            float v = s_P[pb][0][lane] + bVl + ((pm & 1ull) ? eW3 : eW2);
            float e = __expf(v) - 1.0f;
            s_h[0][lane] = (v > 0.f) ? v : e;
        }
        unsigned long long hm = cm;        // bit0 = hsel at step 1
        unsigned long long vm = pm >> 1;   // bit0 = vsel at step 1

        // ---- steps 1..63: 8 broadcast LDS.128 feed BOTH WcH and WcV.
        //      NO warpsync: the per-warp LSU queue is in-order, so the STS of
        //      h_{j-1} (issued by this same warp last iteration) commits before
        //      this iteration's LDS reads it. Compiler barrier pins program order.
#pragma unroll 3
        for (int j = 1; j < LSZ; ++j) {
            float Pj = s_P[pb][j][lane];   // same-lane, independent of h
            float hsel = (hm & 1ull) ? W1 : W0;
            float vsel = (vm & 1ull) ? eW3 : eW2;
            hm >>= 1; vm >>= 1;
            float base = (Pj + bVl) + (hsel + vsel);

            asm volatile("" ::: "memory"); // order prior STS before these LDS
            const float4* hp = reinterpret_cast<const float4*>(&s_h[j - 1][0]);
            float4 g0 = hp[0], g1 = hp[1], g2 = hp[2], g3 = hp[3];
            float4 g4 = hp[4], g5 = hp[5], g6 = hp[6], g7 = hp[7];

            float2 aH0 = make_float2(0.f, 0.f), aH1 = aH0, aH2 = aH0, aH3 = aH0;
            float2 aV0 = aH0, aV1 = aH0, aV2 = aH0, aV3 = aH0;
            float2 p0 = make_float2(g0.x, g0.y), p1 = make_float2(g0.z, g0.w);
            float2 p2 = make_float2(g1.x, g1.y), p3 = make_float2(g1.z, g1.w);
            float2 p4 = make_float2(g2.x, g2.y), p5 = make_float2(g2.z, g2.w);
            float2 p6 = make_float2(g3.x, g3.y), p7 = make_float2(g3.z, g3.w);
            aH0 = ffma2(WH[0], p0, aH0);  aV0 = ffma2(WV[0], p0, aV0);
            aH1 = ffma2(WH[1], p1, aH1);  aV1 = ffma2(WV[1], p1, aV1);
            aH2 = ffma2(WH[2], p2, aH2);  aV2 = ffma2(WV[2], p2, aV2);
            aH3 = ffma2(WH[3], p3, aH3);  aV3 = ffma2(WV[3], p3, aV3);
            aH0 = ffma2(WH[4], p4, aH0);  aV0 = ffma2(WV[4], p4, aV0);
            aH1 = ffma2(WH[5], p5, aH1);  aV1 = ffma2(WV[5], p5, aV1);
            aH2 = ffma2(WH[6], p6, aH2);  aV2 = ffma2(WV[6], p6, aV2);
            aH3 = ffma2(WH[7], p7, aH3);  aV3 = ffma2(WV[7], p7, aV3);
            p0 = make_float2(g4.x, g4.y); p1 = make_float2(g4.z, g4.w);
            p2 = make_float2(g5.x, g5.y); p3 = make_float2(g5.z, g5.w);
            p4 = make_float2(g6.x, g6.y); p5 = make_float2(g6.z, g6.w);
            p6 = make_float2(g7.x, g7.y); p7 = make_float2(g7.z, g7.w);
            aH0 = ffma2(WH[8],  p0, aH0); aV0 = ffma2(WV[8],  p0, aV0);
            aH1 = ffma2(WH[9],  p1, aH1); aV1 = ffma2(WV[9],  p1, aV1);
            aH2 = ffma2(WH[10], p2, aH2); aV2 = ffma2(WV[10], p2, aV2);
            aH3 = ffma2(WH[11], p3, aH3); aV3 = ffma2(WV[11], p3, aV3);
            aH0 = ffma2(WH[12], p4, aH0); aV0 = ffma2(WV[12], p4, aV0);
            aH1 = ffma2(WH[13], p5, aH1); aV1 = ffma2(WV[13], p5, aV1);
            aH2 = ffma2(WH[14], p6, aH2); aV2 = ffma2(WV[14], p6, aV2);
            aH3 = ffma2(WH[15], p7, aH3); aV3 = ffma2(WV[15], p7, aV3);

            float2 sV = fadd2(fadd2(aV0, aV1), fadd2(aV2, aV3));
            s_P[nb][LSZ - j][lane] = sV.x + sV.y;   // h_{j-1} -> next row scan 64-j

            float2 sH = fadd2(fadd2(aH0, aH1), fadd2(aH2, aH3));
            float v = (sH.x + sH.y) + base;
            float e = __expf(v) - 1.0f;
            s_h[j][lane] = (v > 0.f) ? v : e;
        }

        // ---- tail: vertical contribution of h_63 -> next row scan 0 ----
        {
            __syncwarp();
            const float4* hp = reinterpret_cast<const float4*>(&s_h[LSZ - 1][0]);
            float2 aV0 = make_float2(0.f, 0.f), aV1 = aV0, aV2 = aV0, aV3 = aV0;
#pragma unroll
            for (int m = 0; m < 8; ++m) {
                float4 g = hp[m];
                float2 q0 = make_float2(g.x, g.y);
                float2 q1 = make_float2(g.z, g.w);
                aV0 = ffma2(WV[2 * m],     q0, aV0);
                aV1 = ffma2(WV[2 * m + 1], q1, aV1);
            }
            float2 sV = fadd2(fadd2(aV0, aV1), fadd2(aV2, aV3));
            s_P[nb][0][lane] = sV.x + sV.y;
        }

        // ---- epilogue: per-column 2-class log-softmax (lane owns cols lane, lane+32)
        const float* hb = &s_h[0][0];
        const int l32 = lane * HSZ;
        float d0 = 0.f, d1 = 0.f;
#pragma unroll
        for (int m = 0; m < 32; ++m) {
            int   idx = lane ^ m;          // conflict-free rotation
            float wv  = s_wod[idx];
            d0 = fmaf(hb[l32 + idx],             wv, d0);
            d1 = fmaf(hb[l32 + HSZ * HSZ + idx], wv, d1);
        }
        float u0 = d0 + bd, u1 = d1 + bd;  // z0 - z1 per column
        int sp0 = (int)((cm >> lane) & 1ull);
        int sp1 = (int)((cm >> (lane + 32)) & 1ull);
        float t0 = sp0 ? u0 : -u0;
        float t1 = sp1 ? u1 : -u1;
        float lp0 = -fmaxf(t0, 0.f) - log1pf(__expf(-fabsf(t0)));
        float lp1 = -fmaxf(t1, 0.f) - log1pf(__expf(-fabsf(t1)));
        if (isnan(lp0)) lp0 = -35.f;
        if (isnan(lp1)) lp1 = -35.f;
        lanesum += lp0 + lp1;
        __syncwarp();                      // epilogue reads done before next row's STS
    }

    float tot = lanesum;
#pragma unroll
    for (int off = 16; off; off >>= 1)
        tot += __shfl_xor_sync(FULLMASK, tot, off);
    if (lane == 0) out[b] = 0.5f * tot;
}

extern "C" void kernel_launch(void* const* d_in, const int* in_sizes, int n_in,
                              void* d_out, int out_size)
{
    const int*   x    = (const int*)  d_in[0];
    const float* Win  = (const float*)d_in[1];
    const float* WcH  = (const float*)d_in[2];
    const float* WcV  = (const float*)d_in[3];
    const float* bV   = (const float*)d_in[4];
    const float* Wout = (const float*)d_in[5];
    const float* bout = (const float*)d_in[6];

    rnn2d_kernel<<<BATCH, 32>>>(x, Win, WcH, WcV, bV, Wout, bout, (float*)d_out);
}